// round 3
// baseline (speedup 1.0000x reference)
#include <cuda_runtime.h>
#include <cuda_bf16.h>
#include <cstdio>
#include <cmath>

// Problem constants
#define Bq   32
#define Tq   2048
#define Dq   512
#define Hq   512
#define Lq   2
#define G4   2048          // 4*H

#define REC_NCTA 128
#define NTHR     256

// ---------------------------------------------------------------------------
// Scratch (device globals — no allocation allowed)
// ---------------------------------------------------------------------------
__device__ float    g_G[(size_t)Tq * G4 * Bq];     // [t][r][b]  precomputed gates, 536 MB
__device__ float    g_hseq[(size_t)Tq * Hq * Bq];  // [t][j][b]  layer0 output seq, 134 MB
__device__ float    g_hbuf[2][Hq * Bq];            // [j][b] ping-pong h
__device__ unsigned g_bar;                          // global barrier counter

// ---------------------------------------------------------------------------
// Phase GEMM:  G[t][r][b] = A_row(b,t) . W[r,:] + (b_ih[r] + b_hh[r])
//   mode 0: A rows come from x  [B,T,D]  (row = x + (b*T+t)*D)
//   mode 1: A rows come from g_hseq [t][k][b]
// Tile: 32 b x 128 r, BK=16, 256 threads, 4x4 per-thread tile.
// ---------------------------------------------------------------------------
__global__ __launch_bounds__(NTHR)
void gemm_proj(const float* __restrict__ A,
               const float* __restrict__ Wfull,
               const float* __restrict__ bih,
               const float* __restrict__ bhh,
               int layer, int mode)
{
    __shared__ float As[16 * 33];    // [k][b] pad 33
    __shared__ float Bs[128 * 18];   // [r][k] pad 18

    const int t  = blockIdx.y;
    const int rb = blockIdx.x * 128;
    const float* W = Wfull + (size_t)layer * G4 * Dq;

    const int tid = threadIdx.x;
    const int bq  = tid & 7;        // 0..7  (b quad)
    const int rq  = tid >> 3;       // 0..31 (r quad)

    float acc[4][4];
#pragma unroll
    for (int i = 0; i < 4; ++i)
#pragma unroll
        for (int j = 0; j < 4; ++j) acc[i][j] = 0.f;

    // A-tile load indices
    const int lb  = tid >> 3;        // mode0: b 0..31
    const int lk2 = (tid & 7) * 2;   // mode0: k pair
    // B-tile load indices
    const int br  = tid >> 1;        // 0..127
    const int bkq = (tid & 1) * 8;

    for (int k0 = 0; k0 < Dq; k0 += 16) {
        if (mode == 0) {
            const float2 v = *(const float2*)(A + ((size_t)lb * Tq + t) * Dq + k0 + lk2);
            As[lk2 * 33 + lb]       = v.x;
            As[(lk2 + 1) * 33 + lb] = v.y;
        } else {
            const int fl = tid * 2;
            const int kk = fl >> 5, bb = fl & 31;
            const float2 v = *(const float2*)(g_hseq + (size_t)t * Hq * Bq
                                              + (size_t)(k0 + kk) * Bq + bb);
            As[kk * 33 + bb]     = v.x;
            As[kk * 33 + bb + 1] = v.y;
        }
        {
            const float4 v0 = *(const float4*)(W + (size_t)(rb + br) * Dq + k0 + bkq);
            const float4 v1 = *(const float4*)(W + (size_t)(rb + br) * Dq + k0 + bkq + 4);
            float* p = Bs + br * 18 + bkq;
            p[0] = v0.x; p[1] = v0.y; p[2] = v0.z; p[3] = v0.w;
            p[4] = v1.x; p[5] = v1.y; p[6] = v1.z; p[7] = v1.w;
        }
        __syncthreads();
#pragma unroll
        for (int k = 0; k < 16; ++k) {
            float a0 = As[k * 33 + bq * 4 + 0];
            float a1 = As[k * 33 + bq * 4 + 1];
            float a2 = As[k * 33 + bq * 4 + 2];
            float a3 = As[k * 33 + bq * 4 + 3];
            float w0 = Bs[(rq * 4 + 0) * 18 + k];
            float w1 = Bs[(rq * 4 + 1) * 18 + k];
            float w2 = Bs[(rq * 4 + 2) * 18 + k];
            float w3 = Bs[(rq * 4 + 3) * 18 + k];
            acc[0][0] += w0 * a0; acc[0][1] += w0 * a1; acc[0][2] += w0 * a2; acc[0][3] += w0 * a3;
            acc[1][0] += w1 * a0; acc[1][1] += w1 * a1; acc[1][2] += w1 * a2; acc[1][3] += w1 * a3;
            acc[2][0] += w2 * a0; acc[2][1] += w2 * a1; acc[2][2] += w2 * a2; acc[2][3] += w2 * a3;
            acc[3][0] += w3 * a0; acc[3][1] += w3 * a1; acc[3][2] += w3 * a2; acc[3][3] += w3 * a3;
        }
        __syncthreads();
    }

    const size_t gbase = (size_t)t * G4 * Bq;
#pragma unroll
    for (int ri = 0; ri < 4; ++ri) {
        const int r = rb + rq * 4 + ri;
        const float bv = bih[layer * G4 + r] + bhh[layer * G4 + r];
        float4 o4;
        o4.x = acc[ri][0] + bv;
        o4.y = acc[ri][1] + bv;
        o4.z = acc[ri][2] + bv;
        o4.w = acc[ri][3] + bv;
        *(float4*)(g_G + gbase + (size_t)r * Bq + bq * 4) = o4;
    }
}

// ---------------------------------------------------------------------------
// Persistent recurrent kernel (one launch per layer).
// 128 CTAs x 256 threads, CTA owns hidden columns j in [cta*4, cta*4+4).
// Per step: load h (64KB) -> smem, 16 rows x 32 b dots (K split 8 ways across
// warps), smem reduce, activations, write h + outputs, global spin barrier.
// ---------------------------------------------------------------------------
// shared layout (floats):
//   W_sh  : 16*513            = 8208
//   h_sh  : 512*32            = 16384
//   red   : 8*528             = 4224
//   gsh   : 512
//   hstage: 128
#define SH_WS   0
#define SH_HS   (16 * 513)
#define SH_RED  (SH_HS + Hq * Bq)
#define SH_GSH  (SH_RED + 8 * 528)
#define SH_HST  (SH_GSH + 512)
#define SH_TOTF (SH_HST + 128)

__global__ __launch_bounds__(NTHR)
void lstm_rec(const float* __restrict__ h0,
              const float* __restrict__ c0,
              const float* __restrict__ Whh_full,
              float* __restrict__ out,
              int layer)
{
    extern __shared__ float sh[];
    float* W_sh   = sh + SH_WS;
    float* h_sh   = sh + SH_HS;
    float* red    = sh + SH_RED;
    float* gsh    = sh + SH_GSH;
    float* hstage = sh + SH_HST;

    const int tid   = threadIdx.x;
    const int cta   = blockIdx.x;
    const int jbase = cta * 4;
    const float* Whh = Whh_full + (size_t)layer * G4 * Hq;

    // Load this CTA's 16 Whh rows (gate*512 + jbase + jl) into shared.
    for (int idx = tid; idx < 16 * Hq; idx += NTHR) {
        const int r_idx = idx >> 9, k = idx & 511;
        const int gate = r_idx >> 2, jl0 = r_idx & 3;
        W_sh[r_idx * 513 + k] = Whh[(size_t)(gate * Hq + jbase + jl0) * Hq + k];
    }

    // Init hbuf[0] from h0 (transposed to [j][b]); first 64 CTAs cover 16384 elems.
    if (cta < 64) {
        const int idx = cta * NTHR + tid;
        const int j = idx >> 5, b = idx & 31;
        g_hbuf[0][idx] = h0[(size_t)layer * Bq * Hq + (size_t)b * Hq + j];
    }

    // Cell state lives in registers of the 128 activation threads.
    const int bb = tid & 31;
    const int jl = tid >> 5;     // valid gate-thread mapping for tid < 128
    float c_reg = 0.f;
    if (tid < 128) c_reg = c0[(size_t)layer * Bq * Hq + (size_t)bb * Hq + jbase + jl];

    const int w    = tid >> 5;   // warp = k-slice (0..7)
    const int lane = tid & 31;
    const int bq   = lane & 7;
    const int rq   = lane >> 3;
    const int k0   = w * 64;

    unsigned gen = 0;
    for (int t = 0; t < Tq; ++t) {
        // ---- global barrier: everything from prev step (and init) done ----
        gen += REC_NCTA;
        __threadfence();
        __syncthreads();
        if (tid == 0) {
            atomicAdd(&g_bar, 1u);
            while (*(volatile unsigned*)&g_bar < gen) __nanosleep(32);
            __threadfence();
        }
        __syncthreads();

        const int cur = t & 1;

        // ---- broadcast h into shared ----
        {
            const float4* src = (const float4*)g_hbuf[cur];
            float4* dst = (float4*)h_sh;
#pragma unroll
            for (int i = 0; i < 16; ++i) dst[tid + i * NTHR] = src[tid + i * NTHR];
        }
        __syncthreads();

        // ---- partial dot products: 16 outputs/thread over k-slice of 64 ----
        float acc[4][4];
#pragma unroll
        for (int i = 0; i < 4; ++i)
#pragma unroll
            for (int j = 0; j < 4; ++j) acc[i][j] = 0.f;

#pragma unroll 4
        for (int k = k0; k < k0 + 64; ++k) {
            const float h0v = h_sh[k * 32 + bq * 4 + 0];
            const float h1v = h_sh[k * 32 + bq * 4 + 1];
            const float h2v = h_sh[k * 32 + bq * 4 + 2];
            const float h3v = h_sh[k * 32 + bq * 4 + 3];
            const float w0 = W_sh[(rq * 4 + 0) * 513 + k];
            const float w1 = W_sh[(rq * 4 + 1) * 513 + k];
            const float w2 = W_sh[(rq * 4 + 2) * 513 + k];
            const float w3 = W_sh[(rq * 4 + 3) * 513 + k];
            acc[0][0] += w0 * h0v; acc[0][1] += w0 * h1v; acc[0][2] += w0 * h2v; acc[0][3] += w0 * h3v;
            acc[1][0] += w1 * h0v; acc[1][1] += w1 * h1v; acc[1][2] += w1 * h2v; acc[1][3] += w1 * h3v;
            acc[2][0] += w2 * h0v; acc[2][1] += w2 * h1v; acc[2][2] += w2 * h2v; acc[2][3] += w2 * h3v;
            acc[3][0] += w3 * h0v; acc[3][1] += w3 * h1v; acc[3][2] += w3 * h2v; acc[3][3] += w3 * h3v;
        }

        // ---- stash partials (rq-skew keeps stores conflict-free) ----
#pragma unroll
        for (int ri = 0; ri < 4; ++ri)
#pragma unroll
            for (int bi = 0; bi < 4; ++bi) {
                const int o = (rq * 4 + ri) * 32 + bq * 4 + bi;
                red[w * 528 + o + rq] = acc[ri][bi];
            }
        __syncthreads();

        // ---- reduce 8 k-slices + add precomputed input gates ----
#pragma unroll
        for (int rep = 0; rep < 2; ++rep) {
            const int o = tid + rep * NTHR;
            const int skew = o + (o >> 7);
            float s = 0.f;
#pragma unroll
            for (int ww = 0; ww < 8; ++ww) s += red[ww * 528 + skew];
            const int r_idx = o >> 5, bo = o & 31;
            const int gate = r_idx >> 2, jj = r_idx & 3;
            s += g_G[(size_t)t * G4 * Bq + (size_t)(gate * Hq + jbase + jj) * Bq + bo];
            gsh[o] = s;
        }
        __syncthreads();

        // ---- activations + state update (torch gate order i,f,g,o) ----
        if (tid < 128) {
            const float xi = gsh[(0 * 4 + jl) * 32 + bb];
            const float xf = gsh[(1 * 4 + jl) * 32 + bb];
            const float xg = gsh[(2 * 4 + jl) * 32 + bb];
            const float xo = gsh[(3 * 4 + jl) * 32 + bb];
            const float ig = 1.f / (1.f + expf(-xi));
            const float fg = 1.f / (1.f + expf(-xf));
            const float gg = tanhf(xg);
            const float og = 1.f / (1.f + expf(-xo));
            c_reg = fg * c_reg + ig * gg;
            const float hv = og * tanhf(c_reg);
            const int j = jbase + jl;

            g_hbuf[cur ^ 1][j * 32 + bb] = hv;

            if (layer == 0) {
                g_hseq[(size_t)t * Hq * Bq + (size_t)j * Bq + bb] = hv;   // [t][j][b]
            } else {
                hstage[bb * 4 + jl] = hv;
            }
            if (t == Tq - 1) {
                out[(size_t)Bq * Tq * Hq + (size_t)layer * Bq * Hq + (size_t)bb * Hq + j] = hv;
                out[(size_t)Bq * Tq * Hq + (size_t)Lq * Bq * Hq
                    + (size_t)layer * Bq * Hq + (size_t)bb * Hq + j] = c_reg;
            }
        }
        if (layer == 1) {
            __syncthreads();
            if (tid < 32) {
                const float4 v = *(const float4*)(hstage + tid * 4);
                *(float4*)(out + ((size_t)tid * Tq + t) * Hq + jbase) = v;   // [b][t][j]
            }
        }
        // next iteration's top barrier doubles as the step fence
    }
}

// ---------------------------------------------------------------------------
// Launch: proj0 -> rec0 -> proj1 -> rec1  (all graph-capturable)
// ---------------------------------------------------------------------------
extern "C" void kernel_launch(void* const* d_in, const int* in_sizes, int n_in,
                              void* d_out, int out_size)
{
    const float* x    = (const float*)d_in[0];
    const float* h0   = (const float*)d_in[1];
    const float* c0   = (const float*)d_in[2];
    const float* Wih  = (const float*)d_in[3];
    const float* Whh  = (const float*)d_in[4];
    const float* bih  = (const float*)d_in[5];
    const float* bhh  = (const float*)d_in[6];
    float* out = (float*)d_out;

    cudaFuncSetAttribute(lstm_rec, cudaFuncAttributeMaxDynamicSharedMemorySize,
                         SH_TOTF * (int)sizeof(float));

    void* barp = nullptr;
    cudaGetSymbolAddress(&barp, g_bar);

    const dim3 ggrid(G4 / 128, Tq);
    const size_t shmem = SH_TOTF * sizeof(float);

    // Layer 0
    gemm_proj<<<ggrid, NTHR>>>(x, Wih, bih, bhh, 0, 0);
    cudaMemsetAsync(barp, 0, sizeof(unsigned), 0);
    lstm_rec<<<REC_NCTA, NTHR, shmem>>>(h0, c0, Whh, out, 0);

    // Layer 1
    gemm_proj<<<ggrid, NTHR>>>(x /*unused in mode 1*/, Wih, bih, bhh, 1, 1);
    cudaMemsetAsync(barp, 0, sizeof(unsigned), 0);
    lstm_rec<<<REC_NCTA, NTHR, shmem>>>(h0, c0, Whh, out, 1);
}

// round 12
// speedup vs baseline: 1.1192x; 1.1192x over previous
#include <cuda_runtime.h>
#include <cuda_bf16.h>
#include <mma.h>
#include <cstdint>
#include <cmath>

using namespace nvcuda;

// Problem constants
#define Bq   32
#define Tq   2048
#define Dq   512
#define Hq   512
#define Lq   2
#define G4   2048          // 4*H

#define REC_NCTA 128
#define NTHR     256

// ===========================================================================
// Scratch (device globals)
// ===========================================================================
__device__ float            g_G[(size_t)Tq * G4 * Bq];      // [t][r][b] gates
__device__ __nv_bfloat162   g_xsplit[(size_t)Bq * Tq * Dq]; // [b][t][k] {hi,lo}
__device__ __nv_bfloat162   g_hsplit[(size_t)Tq * Bq * Hq]; // [t][b][j] {hi,lo}
__device__ __nv_bfloat162   g_wsplit[(size_t)Lq * G4 * Dq]; // [l][r][k] {hi,lo}
__device__ float            g_hbuf[2][Hq * Bq];             // [j][b] ping-pong h
__device__ unsigned         g_bar;

// ===========================================================================
// fp32 -> (bf16 hi, bf16 lo) split conversion, vectorized
// ===========================================================================
__device__ __forceinline__ __nv_bfloat162 split2(float v) {
    __nv_bfloat16 hi = __float2bfloat16(v);
    __nv_bfloat16 lo = __float2bfloat16(v - __bfloat162float(hi));
    __nv_bfloat162 p; p.x = hi; p.y = lo;
    return p;
}
__global__ __launch_bounds__(256)
void conv_split(const float* __restrict__ src, __nv_bfloat162* __restrict__ dst, int n4) {
    int i = blockIdx.x * 256 + threadIdx.x;
    if (i >= n4) return;
    float4 v = ((const float4*)src)[i];
    uint2* d = (uint2*)(dst + (size_t)i * 4);
    __nv_bfloat162 p0 = split2(v.x), p1 = split2(v.y), p2 = split2(v.z), p3 = split2(v.w);
    uint2 o0, o1;
    o0.x = *(uint32_t*)&p0; o0.y = *(uint32_t*)&p1;
    o1.x = *(uint32_t*)&p2; o1.y = *(uint32_t*)&p3;
    d[0] = o0; d[1] = o1;
}

// ===========================================================================
// WMMA (HMMA) projection GEMM:
//   G[t][r][b] = sum_k W[r][k] * X[(t,b)][k] + bias[r]
//   split-bf16, 3 terms: WhiXhi + WhiXlo + WloXhi, fp32 accumulate.
// CTA: 256 threads (8 warps, 4x2). Tile M=128 (r), N=64 (2 t x 32 b), K=64
// chunks. W smem [r][k] row-major pad 72; X smem [n][k] pad 72 (col_major B).
// mode 0: X = g_xsplit [b][t][k]; mode 1: X = g_hsplit [t][b][j].
// ===========================================================================
#define KP      72                 // padded K stride (bf16 elems)
#define SW_HI   0                  // 128*72*2 = 18432 B
#define SW_LO   18432
#define SX_HI   36864              // 64*72*2 = 9216 B
#define SX_LO   46080
#define P_SMEM  55296
#define STG_LD  68                 // fp32 stage leading dim

__global__ __launch_bounds__(NTHR)
void proj_wmma(const float* __restrict__ bih, const float* __restrict__ bhh,
               int layer, int mode)
{
    extern __shared__ char psm[];
    __nv_bfloat16* Whi = (__nv_bfloat16*)(psm + SW_HI);
    __nv_bfloat16* Wlo = (__nv_bfloat16*)(psm + SW_LO);
    __nv_bfloat16* Xhi = (__nv_bfloat16*)(psm + SX_HI);
    __nv_bfloat16* Xlo = (__nv_bfloat16*)(psm + SX_LO);

    const int tid = threadIdx.x;
    const int wid = tid >> 5;
    const int wm  = wid & 3;            // warp row (4)  -> rows wm*32..+32
    const int wn  = wid >> 2;           // warp col (2)  -> cols wn*32..+32
    const int rb  = blockIdx.x * 128;   // gate-row tile base
    const int nb  = blockIdx.y * 64;    // global col base (t,b)

    wmma::fragment<wmma::accumulator, 16, 16, 16, float> acc[2][2];
#pragma unroll
    for (int i = 0; i < 2; ++i)
#pragma unroll
        for (int j = 0; j < 2; ++j) wmma::fill_fragment(acc[i][j], 0.f);

    const __nv_bfloat162* wsrc = g_wsplit + (size_t)(layer * G4 + rb) * Dq;
    const __nv_bfloat162* xs   = (mode == 0 ? g_xsplit : g_hsplit);

    for (int ch = 0; ch < 8; ++ch) {
        const int k0 = ch * 64;

        // ---- W tile: 128 rows x 64 k, deinterleave {hi,lo} ----
#pragma unroll
        for (int it = 0; it < 8; ++it) {
            const int idx = tid + it * 256;     // 0..2047
            const int row = idx >> 4;
            const int c   = idx & 15;           // 4-k group
            const uint4 u = *(const uint4*)(wsrc + (size_t)row * Dq + k0 + c * 4);
            uint2 h, l;
            h.x = (u.x & 0xFFFFu) | (u.y << 16);
            h.y = (u.z & 0xFFFFu) | (u.w << 16);
            l.x = (u.x >> 16) | (u.y & 0xFFFF0000u);
            l.y = (u.z >> 16) | (u.w & 0xFFFF0000u);
            const int eo = row * KP + c * 4;
            *(uint2*)(Whi + eo) = h;
            *(uint2*)(Wlo + eo) = l;
        }
        // ---- X tile: 64 n-rows x 64 k ----
#pragma unroll
        for (int it = 0; it < 4; ++it) {
            const int idx = tid + it * 256;     // 0..1023
            const int n   = idx >> 4;
            const int c   = idx & 15;
            const int ng  = nb + n;
            const int t   = ng >> 5;
            const int b   = ng & 31;
            const size_t goff = (mode == 0)
                ? ((size_t)b * Tq + t) * Dq
                : ((size_t)t * Bq + b) * Hq;
            const uint4 u = *(const uint4*)(xs + goff + k0 + c * 4);
            uint2 h, l;
            h.x = (u.x & 0xFFFFu) | (u.y << 16);
            h.y = (u.z & 0xFFFFu) | (u.w << 16);
            l.x = (u.x >> 16) | (u.y & 0xFFFF0000u);
            l.y = (u.z >> 16) | (u.w & 0xFFFF0000u);
            const int eo = n * KP + c * 4;
            *(uint2*)(Xhi + eo) = h;
            *(uint2*)(Xlo + eo) = l;
        }
        __syncthreads();

        // ---- compute: 4 k-steps of 16 ----
#pragma unroll
        for (int ks = 0; ks < 4; ++ks) {
            wmma::fragment<wmma::matrix_a, 16, 16, 16, __nv_bfloat16, wmma::row_major> ah[2], al[2];
            wmma::fragment<wmma::matrix_b, 16, 16, 16, __nv_bfloat16, wmma::col_major> bh[2], bl[2];
#pragma unroll
            for (int i = 0; i < 2; ++i) {
                const int ro = (wm * 32 + i * 16) * KP + ks * 16;
                wmma::load_matrix_sync(ah[i], Whi + ro, KP);
                wmma::load_matrix_sync(al[i], Wlo + ro, KP);
            }
#pragma unroll
            for (int j = 0; j < 2; ++j) {
                const int no = (wn * 32 + j * 16) * KP + ks * 16;
                wmma::load_matrix_sync(bh[j], Xhi + no, KP);
                wmma::load_matrix_sync(bl[j], Xlo + no, KP);
            }
#pragma unroll
            for (int i = 0; i < 2; ++i)
#pragma unroll
                for (int j = 0; j < 2; ++j) {
                    wmma::mma_sync(acc[i][j], ah[i], bh[j], acc[i][j]);
                    wmma::mma_sync(acc[i][j], ah[i], bl[j], acc[i][j]);
                    wmma::mma_sync(acc[i][j], al[i], bh[j], acc[i][j]);
                }
        }
        __syncthreads();
    }

    // ---- epilogue: stage fp32, add bias, coalesced stores to g_G ----
    float* stg = (float*)psm;          // 128 x STG_LD
#pragma unroll
    for (int i = 0; i < 2; ++i)
#pragma unroll
        for (int j = 0; j < 2; ++j)
            wmma::store_matrix_sync(stg + (wm * 32 + i * 16) * STG_LD + (wn * 32 + j * 16),
                                    acc[i][j], STG_LD, wmma::mem_row_major);
    __syncthreads();

#pragma unroll
    for (int it = 0; it < 32; ++it) {
        const int o = tid + it * 256;       // 0..8191
        const int r = o >> 6;               // 0..127
        const int n = o & 63;
        const int ng = nb + n;
        const int t  = ng >> 5;
        const int b  = ng & 31;
        const int rg = rb + r;
        const float bv = bih[layer * G4 + rg] + bhh[layer * G4 + rg];
        g_G[(size_t)t * G4 * Bq + (size_t)rg * Bq + b] = stg[r * STG_LD + n] + bv;
    }
}

// ===========================================================================
// Persistent recurrent kernel (one launch per layer). Whh stored transposed
// [k][16] for LDS.128; layer 0 emits h as interleaved bf16 hi/lo pairs for
// the layer-1 projection.
// ===========================================================================
#define SH_WS   0
#define SH_HS   (16 * 512)
#define SH_RED  (SH_HS + Hq * Bq)
#define SH_GSH  (SH_RED + 8 * 528)
#define SH_HST  (SH_GSH + 512)
#define SH_TOTF (SH_HST + 128)

__global__ __launch_bounds__(NTHR)
void lstm_rec(const float* __restrict__ h0,
              const float* __restrict__ c0,
              const float* __restrict__ Whh_full,
              float* __restrict__ out,
              int layer)
{
    extern __shared__ float sh[];
    float* W_sh   = sh + SH_WS;     // [k][16]
    float* h_sh   = sh + SH_HS;     // [k][32]
    float* red    = sh + SH_RED;
    float* gsh    = sh + SH_GSH;
    float* hstage = sh + SH_HST;

    const int tid   = threadIdx.x;
    const int cta   = blockIdx.x;
    const int jbase = cta * 4;
    const float* Whh = Whh_full + (size_t)layer * G4 * Hq;

    // Whh rows for this CTA, transposed into [k][16]
    for (int idx = tid; idx < 2048; idx += NTHR) {
        const int r16 = idx & 15;
        const int k4  = (idx >> 4) * 4;
        const int gate = r16 >> 2, jl0 = r16 & 3;
        const float4 v = *(const float4*)(Whh + (size_t)(gate * Hq + jbase + jl0) * Hq + k4);
        W_sh[(k4 + 0) * 16 + r16] = v.x;
        W_sh[(k4 + 1) * 16 + r16] = v.y;
        W_sh[(k4 + 2) * 16 + r16] = v.z;
        W_sh[(k4 + 3) * 16 + r16] = v.w;
    }

    if (cta < 64) {
        const int idx = cta * NTHR + tid;
        const int j = idx >> 5, b = idx & 31;
        g_hbuf[0][idx] = h0[(size_t)layer * Bq * Hq + (size_t)b * Hq + j];
    }

    const int bb = tid & 31;
    const int jl = tid >> 5;
    float c_reg = 0.f;
    if (tid < 128) c_reg = c0[(size_t)layer * Bq * Hq + (size_t)bb * Hq + jbase + jl];

    const int w    = tid >> 5;
    const int lane = tid & 31;
    const int bq   = lane & 7;
    const int rq   = lane >> 3;
    const int k0   = w * 64;

    unsigned gen = 0;
    for (int t = 0; t < Tq; ++t) {
        gen += REC_NCTA;
        __threadfence();
        __syncthreads();
        if (tid == 0) {
            atomicAdd(&g_bar, 1u);
            while (*(volatile unsigned*)&g_bar < gen) __nanosleep(32);
            __threadfence();
        }
        __syncthreads();

        const int cur = t & 1;
        {
            const float4* src = (const float4*)g_hbuf[cur];
            float4* dst = (float4*)h_sh;
#pragma unroll
            for (int i = 0; i < 16; ++i) dst[tid + i * NTHR] = src[tid + i * NTHR];
        }
        __syncthreads();

        float acc[4][4];
#pragma unroll
        for (int i = 0; i < 4; ++i)
#pragma unroll
            for (int j = 0; j < 4; ++j) acc[i][j] = 0.f;

#pragma unroll 4
        for (int k = k0; k < k0 + 64; ++k) {
            const float4 hv = *(const float4*)(h_sh + k * 32 + bq * 4);
            const float4 wv = *(const float4*)(W_sh + k * 16 + rq * 4);
            acc[0][0] += wv.x * hv.x; acc[0][1] += wv.x * hv.y; acc[0][2] += wv.x * hv.z; acc[0][3] += wv.x * hv.w;
            acc[1][0] += wv.y * hv.x; acc[1][1] += wv.y * hv.y; acc[1][2] += wv.y * hv.z; acc[1][3] += wv.y * hv.w;
            acc[2][0] += wv.z * hv.x; acc[2][1] += wv.z * hv.y; acc[2][2] += wv.z * hv.z; acc[2][3] += wv.z * hv.w;
            acc[3][0] += wv.w * hv.x; acc[3][1] += wv.w * hv.y; acc[3][2] += wv.w * hv.z; acc[3][3] += wv.w * hv.w;
        }

#pragma unroll
        for (int ri = 0; ri < 4; ++ri)
#pragma unroll
            for (int bi = 0; bi < 4; ++bi) {
                const int o = (rq * 4 + ri) * 32 + bq * 4 + bi;
                red[w * 528 + o + rq] = acc[ri][bi];
            }
        __syncthreads();

#pragma unroll
        for (int rep = 0; rep < 2; ++rep) {
            const int o = tid + rep * NTHR;
            const int skew = o + (o >> 7);
            float s = 0.f;
#pragma unroll
            for (int ww = 0; ww < 8; ++ww) s += red[ww * 528 + skew];
            const int r_idx = o >> 5, bo = o & 31;
            const int gate = r_idx >> 2, jj = r_idx & 3;
            s += g_G[(size_t)t * G4 * Bq + (size_t)(gate * Hq + jbase + jj) * Bq + bo];
            gsh[o] = s;
        }
        __syncthreads();

        if (tid < 128) {
            const float xi = gsh[(0 * 4 + jl) * 32 + bb];
            const float xf = gsh[(1 * 4 + jl) * 32 + bb];
            const float xg = gsh[(2 * 4 + jl) * 32 + bb];
            const float xo = gsh[(3 * 4 + jl) * 32 + bb];
            const float ig = 1.f / (1.f + expf(-xi));
            const float fg = 1.f / (1.f + expf(-xf));
            const float gg = tanhf(xg);
            const float og = 1.f / (1.f + expf(-xo));
            c_reg = fg * c_reg + ig * gg;
            const float hv = og * tanhf(c_reg);
            const int j = jbase + jl;

            g_hbuf[cur ^ 1][j * 32 + bb] = hv;

            if (layer == 0) {
                g_hsplit[(size_t)(t * Bq + bb) * Hq + j] = split2(hv);
            } else {
                hstage[bb * 4 + jl] = hv;
            }
            if (t == Tq - 1) {
                out[(size_t)Bq * Tq * Hq + (size_t)layer * Bq * Hq + (size_t)bb * Hq + j] = hv;
                out[(size_t)Bq * Tq * Hq + (size_t)Lq * Bq * Hq
                    + (size_t)layer * Bq * Hq + (size_t)bb * Hq + j] = c_reg;
            }
        }
        if (layer == 1) {
            __syncthreads();
            if (tid < 32) {
                const float4 v = *(const float4*)(hstage + tid * 4);
                *(float4*)(out + ((size_t)tid * Tq + t) * Hq + jbase) = v;
            }
        }
    }
}

// ===========================================================================
// Launch: conv -> proj0 -> rec0 -> proj1 -> rec1
// ===========================================================================
extern "C" void kernel_launch(void* const* d_in, const int* in_sizes, int n_in,
                              void* d_out, int out_size)
{
    const float* x    = (const float*)d_in[0];
    const float* h0   = (const float*)d_in[1];
    const float* c0   = (const float*)d_in[2];
    const float* Wih  = (const float*)d_in[3];
    const float* Whh  = (const float*)d_in[4];
    const float* bih  = (const float*)d_in[5];
    const float* bhh  = (const float*)d_in[6];
    float* out = (float*)d_out;

    cudaFuncSetAttribute(lstm_rec, cudaFuncAttributeMaxDynamicSharedMemorySize,
                         SH_TOTF * (int)sizeof(float));
    cudaFuncSetAttribute(proj_wmma, cudaFuncAttributeMaxDynamicSharedMemorySize, P_SMEM);

    void* barp = nullptr;
    cudaGetSymbolAddress(&barp, g_bar);

    __nv_bfloat162* xs = nullptr; cudaGetSymbolAddress((void**)&xs, g_xsplit);
    __nv_bfloat162* ws = nullptr; cudaGetSymbolAddress((void**)&ws, g_wsplit);

    const size_t rsh = SH_TOTF * sizeof(float);
    const dim3 pgrid(G4 / 128, (Tq * Bq) / 64);

    // bf16 split conversions
    {
        const int n4x = Bq * Tq * Dq / 4;
        conv_split<<<(n4x + 255) / 256, 256>>>(x, xs, n4x);
        const int n4w = Lq * G4 * Dq / 4;
        conv_split<<<(n4w + 255) / 256, 256>>>(Wih, ws, n4w);
    }

    // Layer 0
    proj_wmma<<<pgrid, NTHR, P_SMEM>>>(bih, bhh, 0, 0);
    cudaMemsetAsync(barp, 0, sizeof(unsigned), 0);
    lstm_rec<<<REC_NCTA, NTHR, rsh>>>(h0, c0, Whh, out, 0);

    // Layer 1
    proj_wmma<<<pgrid, NTHR, P_SMEM>>>(bih, bhh, 1, 1);
    cudaMemsetAsync(barp, 0, sizeof(unsigned), 0);
    lstm_rec<<<REC_NCTA, NTHR, rsh>>>(h0, c0, Whh, out, 1);
}

// round 14
// speedup vs baseline: 1.3273x; 1.1859x over previous
#include <cuda_runtime.h>
#include <cuda_bf16.h>
#include <mma.h>
#include <cstdint>
#include <cmath>

using namespace nvcuda;

// Problem constants
#define Bq   32
#define Tq   2048
#define Dq   512
#define Hq   512
#define Lq   2
#define G4   2048          // 4*H

#define REC_NCTA 128
#define NTHR     256

// ===========================================================================
// Scratch (device globals)
// ===========================================================================
__device__ float            g_G[(size_t)Tq * G4 * Bq];      // [t][r][b] gates
__device__ __nv_bfloat162   g_xsplit[(size_t)Bq * Tq * Dq]; // [b][t][k] {hi,lo}
__device__ __nv_bfloat162   g_hsplit[(size_t)Tq * Bq * Hq]; // [t][b][j] {hi,lo}
__device__ __nv_bfloat162   g_wsplit[(size_t)Lq * G4 * Dq]; // [l][r][k] {hi,lo}
__device__ __nv_bfloat16    g_hb_hi[2][Hq * Bq];            // [j][b] ping-pong h hi
__device__ __nv_bfloat16    g_hb_lo[2][Hq * Bq];            // [j][b] ping-pong h lo
__device__ unsigned         g_bar;

// ===========================================================================
// fp32 -> (bf16 hi, bf16 lo) split conversion, vectorized
// ===========================================================================
__device__ __forceinline__ __nv_bfloat162 split2(float v) {
    __nv_bfloat16 hi = __float2bfloat16(v);
    __nv_bfloat16 lo = __float2bfloat16(v - __bfloat162float(hi));
    __nv_bfloat162 p; p.x = hi; p.y = lo;
    return p;
}
__global__ __launch_bounds__(256)
void conv_split(const float* __restrict__ src, __nv_bfloat162* __restrict__ dst, int n4) {
    int i = blockIdx.x * 256 + threadIdx.x;
    if (i >= n4) return;
    float4 v = ((const float4*)src)[i];
    uint2* d = (uint2*)(dst + (size_t)i * 4);
    __nv_bfloat162 p0 = split2(v.x), p1 = split2(v.y), p2 = split2(v.z), p3 = split2(v.w);
    uint2 o0, o1;
    o0.x = *(uint32_t*)&p0; o0.y = *(uint32_t*)&p1;
    o1.x = *(uint32_t*)&p2; o1.y = *(uint32_t*)&p3;
    d[0] = o0; d[1] = o1;
}

// ===========================================================================
// WMMA (HMMA) projection GEMM (unchanged from R12 passing version)
// ===========================================================================
#define KP      72
#define SW_HI   0
#define SW_LO   18432
#define SX_HI   36864
#define SX_LO   46080
#define P_SMEM  55296
#define STG_LD  68

__global__ __launch_bounds__(NTHR)
void proj_wmma(const float* __restrict__ bih, const float* __restrict__ bhh,
               int layer, int mode)
{
    extern __shared__ char psm[];
    __nv_bfloat16* Whi = (__nv_bfloat16*)(psm + SW_HI);
    __nv_bfloat16* Wlo = (__nv_bfloat16*)(psm + SW_LO);
    __nv_bfloat16* Xhi = (__nv_bfloat16*)(psm + SX_HI);
    __nv_bfloat16* Xlo = (__nv_bfloat16*)(psm + SX_LO);

    const int tid = threadIdx.x;
    const int wid = tid >> 5;
    const int wm  = wid & 3;
    const int wn  = wid >> 2;
    const int rb  = blockIdx.x * 128;
    const int nb  = blockIdx.y * 64;

    wmma::fragment<wmma::accumulator, 16, 16, 16, float> acc[2][2];
#pragma unroll
    for (int i = 0; i < 2; ++i)
#pragma unroll
        for (int j = 0; j < 2; ++j) wmma::fill_fragment(acc[i][j], 0.f);

    const __nv_bfloat162* wsrc = g_wsplit + (size_t)(layer * G4 + rb) * Dq;
    const __nv_bfloat162* xs   = (mode == 0 ? g_xsplit : g_hsplit);

    for (int ch = 0; ch < 8; ++ch) {
        const int k0 = ch * 64;
#pragma unroll
        for (int it = 0; it < 8; ++it) {
            const int idx = tid + it * 256;
            const int row = idx >> 4;
            const int c   = idx & 15;
            const uint4 u = *(const uint4*)(wsrc + (size_t)row * Dq + k0 + c * 4);
            uint2 h, l;
            h.x = (u.x & 0xFFFFu) | (u.y << 16);
            h.y = (u.z & 0xFFFFu) | (u.w << 16);
            l.x = (u.x >> 16) | (u.y & 0xFFFF0000u);
            l.y = (u.z >> 16) | (u.w & 0xFFFF0000u);
            const int eo = row * KP + c * 4;
            *(uint2*)(Whi + eo) = h;
            *(uint2*)(Wlo + eo) = l;
        }
#pragma unroll
        for (int it = 0; it < 4; ++it) {
            const int idx = tid + it * 256;
            const int n   = idx >> 4;
            const int c   = idx & 15;
            const int ng  = nb + n;
            const int t   = ng >> 5;
            const int b   = ng & 31;
            const size_t goff = (mode == 0)
                ? ((size_t)b * Tq + t) * Dq
                : ((size_t)t * Bq + b) * Hq;
            const uint4 u = *(const uint4*)(xs + goff + k0 + c * 4);
            uint2 h, l;
            h.x = (u.x & 0xFFFFu) | (u.y << 16);
            h.y = (u.z & 0xFFFFu) | (u.w << 16);
            l.x = (u.x >> 16) | (u.y & 0xFFFF0000u);
            l.y = (u.z >> 16) | (u.w & 0xFFFF0000u);
            const int eo = n * KP + c * 4;
            *(uint2*)(Xhi + eo) = h;
            *(uint2*)(Xlo + eo) = l;
        }
        __syncthreads();

#pragma unroll
        for (int ks = 0; ks < 4; ++ks) {
            wmma::fragment<wmma::matrix_a, 16, 16, 16, __nv_bfloat16, wmma::row_major> ah[2], al[2];
            wmma::fragment<wmma::matrix_b, 16, 16, 16, __nv_bfloat16, wmma::col_major> bh[2], bl[2];
#pragma unroll
            for (int i = 0; i < 2; ++i) {
                const int ro = (wm * 32 + i * 16) * KP + ks * 16;
                wmma::load_matrix_sync(ah[i], Whi + ro, KP);
                wmma::load_matrix_sync(al[i], Wlo + ro, KP);
            }
#pragma unroll
            for (int j = 0; j < 2; ++j) {
                const int no = (wn * 32 + j * 16) * KP + ks * 16;
                wmma::load_matrix_sync(bh[j], Xhi + no, KP);
                wmma::load_matrix_sync(bl[j], Xlo + no, KP);
            }
#pragma unroll
            for (int i = 0; i < 2; ++i)
#pragma unroll
                for (int j = 0; j < 2; ++j) {
                    wmma::mma_sync(acc[i][j], ah[i], bh[j], acc[i][j]);
                    wmma::mma_sync(acc[i][j], ah[i], bl[j], acc[i][j]);
                    wmma::mma_sync(acc[i][j], al[i], bh[j], acc[i][j]);
                }
        }
        __syncthreads();
    }

    float* stg = (float*)psm;
#pragma unroll
    for (int i = 0; i < 2; ++i)
#pragma unroll
        for (int j = 0; j < 2; ++j)
            wmma::store_matrix_sync(stg + (wm * 32 + i * 16) * STG_LD + (wn * 32 + j * 16),
                                    acc[i][j], STG_LD, wmma::mem_row_major);
    __syncthreads();

#pragma unroll
    for (int it = 0; it < 32; ++it) {
        const int o = tid + it * 256;
        const int r = o >> 6;
        const int n = o & 63;
        const int ng = nb + n;
        const int t  = ng >> 5;
        const int b  = ng & 31;
        const int rg = rb + r;
        const float bv = bih[layer * G4 + rg] + bhh[layer * G4 + rg];
        g_G[(size_t)t * G4 * Bq + (size_t)rg * Bq + b] = stg[r * STG_LD + n] + bv;
    }
}

// ===========================================================================
// Persistent recurrent kernel with HMMA step.
// CTA owns 16 gate-rows (4 gates x 4 j). Per step:
//   h (bf16 hi/lo, [j][b]) -> smem [k][40]; wmma 1m x 2n x 4k per warp
//   (k-slice of 64), 3-term split; partials -> smem; 8-way reduce + g_G;
//   activations; h written back as bf16 hi/lo (+ g_hsplit for layer 0).
// ===========================================================================
#define KP2      520     // W row stride (bf16 elems)
#define HP2      40      // h row stride (bf16 elems)
#define SH2_WHI  0                       // 16*520*2 = 16640
#define SH2_WLO  16640
#define SH2_HHI  33280                   // 512*40*2 = 40960
#define SH2_HLO  74240
#define SH2_RED  115200                  // 8*512*4  = 16384
#define SH2_GSH  131584                  // 512*4
#define SH2_HST  133632                  // 128*4
#define REC_SMEM 134144

__global__ __launch_bounds__(NTHR)
void lstm_rec(const float* __restrict__ h0,
              const float* __restrict__ c0,
              const float* __restrict__ Whh_full,
              float* __restrict__ out,
              int layer)
{
    extern __shared__ char sm2[];
    __nv_bfloat16* W_hi = (__nv_bfloat16*)(sm2 + SH2_WHI);
    __nv_bfloat16* W_lo = (__nv_bfloat16*)(sm2 + SH2_WLO);
    __nv_bfloat16* Hhi  = (__nv_bfloat16*)(sm2 + SH2_HHI);
    __nv_bfloat16* Hlo  = (__nv_bfloat16*)(sm2 + SH2_HLO);
    float* red    = (float*)(sm2 + SH2_RED);
    float* gsh    = (float*)(sm2 + SH2_GSH);
    float* hstage = (float*)(sm2 + SH2_HST);

    const int tid   = threadIdx.x;
    const int cta   = blockIdx.x;
    const int jbase = cta * 4;
    const float* Whh = Whh_full + (size_t)layer * G4 * Hq;

    // Whh rows -> smem bf16 hi/lo, [i][520] (i = gate*4 + jl)
    for (int idx = tid; idx < 16 * Hq; idx += NTHR) {
        const int i = idx >> 9, k = idx & 511;
        const int gate = i >> 2, jl0 = i & 3;
        const __nv_bfloat162 p =
            split2(Whh[(size_t)(gate * Hq + jbase + jl0) * Hq + k]);
        W_hi[i * KP2 + k] = p.x;
        W_lo[i * KP2 + k] = p.y;
    }

    // Init hbuf[0] from h0 (bf16 hi/lo, [j][b])
    if (cta < 64) {
        const int idx = cta * NTHR + tid;
        const int j = idx >> 5, b = idx & 31;
        const __nv_bfloat162 p =
            split2(h0[(size_t)layer * Bq * Hq + (size_t)b * Hq + j]);
        g_hb_hi[0][idx] = p.x;
        g_hb_lo[0][idx] = p.y;
    }

    const int bb = tid & 31;
    const int jl = tid >> 5;
    float c_reg = 0.f;
    if (tid < 128) c_reg = c0[(size_t)layer * Bq * Hq + (size_t)bb * Hq + jbase + jl];

    const int w  = tid >> 5;       // warp -> k-slice (0..7)
    const int k0 = w * 64;

    unsigned gen = 0;
    for (int t = 0; t < Tq; ++t) {
        // ---- global barrier ----
        gen += REC_NCTA;
        __threadfence();
        __syncthreads();
        if (tid == 0) {
            atomicAdd(&g_bar, 1u);
            while (*(volatile unsigned*)&g_bar < gen) __nanosleep(32);
            __threadfence();
        }
        __syncthreads();

        const int cur = t & 1;

        // ---- broadcast h (hi/lo) into smem [k][40] ----
        {
            const uint4* shi = (const uint4*)g_hb_hi[cur];
            const uint4* slo = (const uint4*)g_hb_lo[cur];
#pragma unroll
            for (int it = 0; it < 8; ++it) {
                const int idx = tid + it * NTHR;     // 0..2047 (uint4 = 8 bf16)
                const int row = idx >> 2, c = idx & 3;
                *(uint4*)(Hhi + row * HP2 + c * 8) = shi[idx];
                *(uint4*)(Hlo + row * HP2 + c * 8) = slo[idx];
            }
        }
        __syncthreads();

        // ---- HMMA: 1 m-tile x 2 n-tiles x 4 k-steps, 3-term split ----
        {
            wmma::fragment<wmma::accumulator, 16, 16, 16, float> acc[2];
            wmma::fill_fragment(acc[0], 0.f);
            wmma::fill_fragment(acc[1], 0.f);
#pragma unroll
            for (int ks = 0; ks < 4; ++ks) {
                const int k = k0 + ks * 16;
                wmma::fragment<wmma::matrix_a, 16, 16, 16, __nv_bfloat16, wmma::row_major> a_hi, a_lo;
                wmma::load_matrix_sync(a_hi, W_hi + k, KP2);
                wmma::load_matrix_sync(a_lo, W_lo + k, KP2);
#pragma unroll
                for (int jn = 0; jn < 2; ++jn) {
                    wmma::fragment<wmma::matrix_b, 16, 16, 16, __nv_bfloat16, wmma::row_major> b_hi, b_lo;
                    wmma::load_matrix_sync(b_hi, Hhi + k * HP2 + jn * 16, HP2);
                    wmma::load_matrix_sync(b_lo, Hlo + k * HP2 + jn * 16, HP2);
                    wmma::mma_sync(acc[jn], a_hi, b_hi, acc[jn]);
                    wmma::mma_sync(acc[jn], a_hi, b_lo, acc[jn]);
                    wmma::mma_sync(acc[jn], a_lo, b_hi, acc[jn]);
                }
            }
            wmma::store_matrix_sync(red + w * 512 + 0,  acc[0], 32, wmma::mem_row_major);
            wmma::store_matrix_sync(red + w * 512 + 16, acc[1], 32, wmma::mem_row_major);
        }
        __syncthreads();

        // ---- reduce 8 k-slices + add precomputed input gates ----
#pragma unroll
        for (int rep = 0; rep < 2; ++rep) {
            const int o = tid + rep * NTHR;      // 0..511
            float s = 0.f;
#pragma unroll
            for (int ww = 0; ww < 8; ++ww) s += red[ww * 512 + o];
            const int r_idx = o >> 5, bo = o & 31;
            const int gate = r_idx >> 2, jj = r_idx & 3;
            s += g_G[(size_t)t * G4 * Bq + (size_t)(gate * Hq + jbase + jj) * Bq + bo];
            gsh[o] = s;
        }
        __syncthreads();

        // ---- activations + state update (torch gate order i,f,g,o) ----
        if (tid < 128) {
            const float xi = gsh[(0 * 4 + jl) * 32 + bb];
            const float xf = gsh[(1 * 4 + jl) * 32 + bb];
            const float xg = gsh[(2 * 4 + jl) * 32 + bb];
            const float xo = gsh[(3 * 4 + jl) * 32 + bb];
            const float ig = 1.f / (1.f + expf(-xi));
            const float fg = 1.f / (1.f + expf(-xf));
            const float gg = tanhf(xg);
            const float og = 1.f / (1.f + expf(-xo));
            c_reg = fg * c_reg + ig * gg;
            const float hv = og * tanhf(c_reg);
            const int j = jbase + jl;

            const __nv_bfloat162 hp = split2(hv);
            g_hb_hi[cur ^ 1][j * 32 + bb] = hp.x;
            g_hb_lo[cur ^ 1][j * 32 + bb] = hp.y;

            if (layer == 0) {
                g_hsplit[(size_t)(t * Bq + bb) * Hq + j] = hp;
            } else {
                hstage[bb * 4 + jl] = hv;
            }
            if (t == Tq - 1) {
                out[(size_t)Bq * Tq * Hq + (size_t)layer * Bq * Hq + (size_t)bb * Hq + j] = hv;
                out[(size_t)Bq * Tq * Hq + (size_t)Lq * Bq * Hq
                    + (size_t)layer * Bq * Hq + (size_t)bb * Hq + j] = c_reg;
            }
        }
        if (layer == 1) {
            __syncthreads();
            if (tid < 32) {
                const float4 v = *(const float4*)(hstage + tid * 4);
                *(float4*)(out + ((size_t)tid * Tq + t) * Hq + jbase) = v;
            }
        }
    }
}

// ===========================================================================
// Launch: conv -> proj0 -> rec0 -> proj1 -> rec1
// ===========================================================================
extern "C" void kernel_launch(void* const* d_in, const int* in_sizes, int n_in,
                              void* d_out, int out_size)
{
    const float* x    = (const float*)d_in[0];
    const float* h0   = (const float*)d_in[1];
    const float* c0   = (const float*)d_in[2];
    const float* Wih  = (const float*)d_in[3];
    const float* Whh  = (const float*)d_in[4];
    const float* bih  = (const float*)d_in[5];
    const float* bhh  = (const float*)d_in[6];
    float* out = (float*)d_out;

    cudaFuncSetAttribute(lstm_rec, cudaFuncAttributeMaxDynamicSharedMemorySize, REC_SMEM);
    cudaFuncSetAttribute(proj_wmma, cudaFuncAttributeMaxDynamicSharedMemorySize, P_SMEM);

    void* barp = nullptr;
    cudaGetSymbolAddress(&barp, g_bar);

    __nv_bfloat162* xs = nullptr; cudaGetSymbolAddress((void**)&xs, g_xsplit);
    __nv_bfloat162* ws = nullptr; cudaGetSymbolAddress((void**)&ws, g_wsplit);

    const dim3 pgrid(G4 / 128, (Tq * Bq) / 64);

    // bf16 split conversions
    {
        const int n4x = Bq * Tq * Dq / 4;
        conv_split<<<(n4x + 255) / 256, 256>>>(x, xs, n4x);
        const int n4w = Lq * G4 * Dq / 4;
        conv_split<<<(n4w + 255) / 256, 256>>>(Wih, ws, n4w);
    }

    // Layer 0
    proj_wmma<<<pgrid, NTHR, P_SMEM>>>(bih, bhh, 0, 0);
    cudaMemsetAsync(barp, 0, sizeof(unsigned), 0);
    lstm_rec<<<REC_NCTA, NTHR, REC_SMEM>>>(h0, c0, Whh, out, 0);

    // Layer 1
    proj_wmma<<<pgrid, NTHR, P_SMEM>>>(bih, bhh, 1, 1);
    cudaMemsetAsync(barp, 0, sizeof(unsigned), 0);
    lstm_rec<<<REC_NCTA, NTHR, REC_SMEM>>>(h0, c0, Whh, out, 1);
}

// round 15
// speedup vs baseline: 1.4173x; 1.0678x over previous
#include <cuda_runtime.h>
#include <cuda_bf16.h>
#include <mma.h>
#include <cstdint>
#include <cmath>

using namespace nvcuda;

// Problem constants
#define Bq   32
#define Tq   2048
#define Dq   512
#define Hq   512
#define Lq   2
#define G4   2048          // 4*H

#define REC_NCTA 128
#define NTHR     256

// ===========================================================================
// Scratch (device globals)
// ===========================================================================
__device__ float            g_G[(size_t)Tq * G4 * Bq];      // [t][r][b] gates
__device__ __nv_bfloat162   g_xsplit[(size_t)Bq * Tq * Dq]; // [b][t][k] {hi,lo}
__device__ __nv_bfloat162   g_hsplit[(size_t)Tq * Bq * Hq]; // [t][b][j] {hi,lo}
__device__ __nv_bfloat162   g_wsplit[(size_t)Lq * G4 * Dq]; // [l][r][k] {hi,lo}
__device__ __nv_bfloat16    g_hb_hi[2][Hq * Bq];            // [j][b] ping-pong h hi
__device__ __nv_bfloat16    g_hb_lo[2][Hq * Bq];            // [j][b] ping-pong h lo
__device__ unsigned         g_bar;

// ===========================================================================
// fp32 -> (bf16 hi, bf16 lo) split conversion, vectorized
// ===========================================================================
__device__ __forceinline__ __nv_bfloat162 split2(float v) {
    __nv_bfloat16 hi = __float2bfloat16(v);
    __nv_bfloat16 lo = __float2bfloat16(v - __bfloat162float(hi));
    __nv_bfloat162 p; p.x = hi; p.y = lo;
    return p;
}
__global__ __launch_bounds__(256)
void conv_split(const float* __restrict__ src, __nv_bfloat162* __restrict__ dst, int n4) {
    int i = blockIdx.x * 256 + threadIdx.x;
    if (i >= n4) return;
    float4 v = ((const float4*)src)[i];
    uint2* d = (uint2*)(dst + (size_t)i * 4);
    __nv_bfloat162 p0 = split2(v.x), p1 = split2(v.y), p2 = split2(v.z), p3 = split2(v.w);
    uint2 o0, o1;
    o0.x = *(uint32_t*)&p0; o0.y = *(uint32_t*)&p1;
    o1.x = *(uint32_t*)&p2; o1.y = *(uint32_t*)&p3;
    d[0] = o0; d[1] = o1;
}

// ===========================================================================
// WMMA (HMMA) projection GEMM (unchanged from R12/R14 passing version)
// ===========================================================================
#define KP      72
#define SW_HI   0
#define SW_LO   18432
#define SX_HI   36864
#define SX_LO   46080
#define P_SMEM  55296
#define STG_LD  68

__global__ __launch_bounds__(NTHR)
void proj_wmma(const float* __restrict__ bih, const float* __restrict__ bhh,
               int layer, int mode)
{
    extern __shared__ char psm[];
    __nv_bfloat16* Whi = (__nv_bfloat16*)(psm + SW_HI);
    __nv_bfloat16* Wlo = (__nv_bfloat16*)(psm + SW_LO);
    __nv_bfloat16* Xhi = (__nv_bfloat16*)(psm + SX_HI);
    __nv_bfloat16* Xlo = (__nv_bfloat16*)(psm + SX_LO);

    const int tid = threadIdx.x;
    const int wid = tid >> 5;
    const int wm  = wid & 3;
    const int wn  = wid >> 2;
    const int rb  = blockIdx.x * 128;
    const int nb  = blockIdx.y * 64;

    wmma::fragment<wmma::accumulator, 16, 16, 16, float> acc[2][2];
#pragma unroll
    for (int i = 0; i < 2; ++i)
#pragma unroll
        for (int j = 0; j < 2; ++j) wmma::fill_fragment(acc[i][j], 0.f);

    const __nv_bfloat162* wsrc = g_wsplit + (size_t)(layer * G4 + rb) * Dq;
    const __nv_bfloat162* xs   = (mode == 0 ? g_xsplit : g_hsplit);

    for (int ch = 0; ch < 8; ++ch) {
        const int k0 = ch * 64;
#pragma unroll
        for (int it = 0; it < 8; ++it) {
            const int idx = tid + it * 256;
            const int row = idx >> 4;
            const int c   = idx & 15;
            const uint4 u = *(const uint4*)(wsrc + (size_t)row * Dq + k0 + c * 4);
            uint2 h, l;
            h.x = (u.x & 0xFFFFu) | (u.y << 16);
            h.y = (u.z & 0xFFFFu) | (u.w << 16);
            l.x = (u.x >> 16) | (u.y & 0xFFFF0000u);
            l.y = (u.z >> 16) | (u.w & 0xFFFF0000u);
            const int eo = row * KP + c * 4;
            *(uint2*)(Whi + eo) = h;
            *(uint2*)(Wlo + eo) = l;
        }
#pragma unroll
        for (int it = 0; it < 4; ++it) {
            const int idx = tid + it * 256;
            const int n   = idx >> 4;
            const int c   = idx & 15;
            const int ng  = nb + n;
            const int t   = ng >> 5;
            const int b   = ng & 31;
            const size_t goff = (mode == 0)
                ? ((size_t)b * Tq + t) * Dq
                : ((size_t)t * Bq + b) * Hq;
            const uint4 u = *(const uint4*)(xs + goff + k0 + c * 4);
            uint2 h, l;
            h.x = (u.x & 0xFFFFu) | (u.y << 16);
            h.y = (u.z & 0xFFFFu) | (u.w << 16);
            l.x = (u.x >> 16) | (u.y & 0xFFFF0000u);
            l.y = (u.z >> 16) | (u.w & 0xFFFF0000u);
            const int eo = n * KP + c * 4;
            *(uint2*)(Xhi + eo) = h;
            *(uint2*)(Xlo + eo) = l;
        }
        __syncthreads();

#pragma unroll
        for (int ks = 0; ks < 4; ++ks) {
            wmma::fragment<wmma::matrix_a, 16, 16, 16, __nv_bfloat16, wmma::row_major> ah[2], al[2];
            wmma::fragment<wmma::matrix_b, 16, 16, 16, __nv_bfloat16, wmma::col_major> bh[2], bl[2];
#pragma unroll
            for (int i = 0; i < 2; ++i) {
                const int ro = (wm * 32 + i * 16) * KP + ks * 16;
                wmma::load_matrix_sync(ah[i], Whi + ro, KP);
                wmma::load_matrix_sync(al[i], Wlo + ro, KP);
            }
#pragma unroll
            for (int j = 0; j < 2; ++j) {
                const int no = (wn * 32 + j * 16) * KP + ks * 16;
                wmma::load_matrix_sync(bh[j], Xhi + no, KP);
                wmma::load_matrix_sync(bl[j], Xlo + no, KP);
            }
#pragma unroll
            for (int i = 0; i < 2; ++i)
#pragma unroll
                for (int j = 0; j < 2; ++j) {
                    wmma::mma_sync(acc[i][j], ah[i], bh[j], acc[i][j]);
                    wmma::mma_sync(acc[i][j], ah[i], bl[j], acc[i][j]);
                    wmma::mma_sync(acc[i][j], al[i], bh[j], acc[i][j]);
                }
        }
        __syncthreads();
    }

    float* stg = (float*)psm;
#pragma unroll
    for (int i = 0; i < 2; ++i)
#pragma unroll
        for (int j = 0; j < 2; ++j)
            wmma::store_matrix_sync(stg + (wm * 32 + i * 16) * STG_LD + (wn * 32 + j * 16),
                                    acc[i][j], STG_LD, wmma::mem_row_major);
    __syncthreads();

#pragma unroll
    for (int it = 0; it < 32; ++it) {
        const int o = tid + it * 256;
        const int r = o >> 6;
        const int n = o & 63;
        const int ng = nb + n;
        const int t  = ng >> 5;
        const int b  = ng & 31;
        const int rg = rb + r;
        const float bv = bih[layer * G4 + rg] + bhh[layer * G4 + rg];
        g_G[(size_t)t * G4 * Bq + (size_t)rg * Bq + b] = stg[r * STG_LD + n] + bv;
    }
}

// ===========================================================================
// Persistent recurrent kernel with HMMA step, latency-optimized:
//  - W a-fragments resident in registers (loaded once via transient staging)
//  - g_G[t] prefetched into registers before the global barrier
//  - tight spin (no nanosleep); layer-1 h stored directly to out
// ===========================================================================
#define HP2      40      // h row stride (bf16 elems)
#define SH_HHI   0                       // 512*40*2 = 40960
#define SH_HLO   40960                   // 40960
#define SH_RED   81920                   // 8*512*4  = 16384
#define SH_GSH   98304                   // 512*4
#define REC_SMEM 100352
#define KPW      520     // W staging row stride (bf16 elems)

__global__ __launch_bounds__(NTHR)
void lstm_rec(const float* __restrict__ h0,
              const float* __restrict__ c0,
              const float* __restrict__ Whh_full,
              float* __restrict__ out,
              int layer)
{
    extern __shared__ char sm2[];
    __nv_bfloat16* Hhi = (__nv_bfloat16*)(sm2 + SH_HHI);
    __nv_bfloat16* Hlo = (__nv_bfloat16*)(sm2 + SH_HLO);
    float* red = (float*)(sm2 + SH_RED);
    float* gsh = (float*)(sm2 + SH_GSH);

    const int tid   = threadIdx.x;
    const int cta   = blockIdx.x;
    const int jbase = cta * 4;
    const float* Whh = Whh_full + (size_t)layer * G4 * Hq;

    const int w  = tid >> 5;       // warp -> k-slice (0..7)
    const int k0 = w * 64;

    // ---- one-time: stage Whh rows (bf16 hi/lo) and load a-fragments ----
    wmma::fragment<wmma::matrix_a, 16, 16, 16, __nv_bfloat16, wmma::row_major> a_hi[4], a_lo[4];
    {
        __nv_bfloat16* Wst_hi = (__nv_bfloat16*)(sm2 + 0);       // 16*520*2 = 16640
        __nv_bfloat16* Wst_lo = (__nv_bfloat16*)(sm2 + 16640);   // 16640 (inside H region)
        for (int idx = tid; idx < 16 * Hq; idx += NTHR) {
            const int i = idx >> 9, k = idx & 511;
            const int gate = i >> 2, jl0 = i & 3;
            const __nv_bfloat162 p =
                split2(Whh[(size_t)(gate * Hq + jbase + jl0) * Hq + k]);
            Wst_hi[i * KPW + k] = p.x;
            Wst_lo[i * KPW + k] = p.y;
        }
        __syncthreads();
#pragma unroll
        for (int ks = 0; ks < 4; ++ks) {
            wmma::load_matrix_sync(a_hi[ks], Wst_hi + k0 + ks * 16, KPW);
            wmma::load_matrix_sync(a_lo[ks], Wst_lo + k0 + ks * 16, KPW);
        }
        __syncthreads();   // staging region is reused for H below
    }

    // Init hbuf[0] from h0 (bf16 hi/lo, [j][b])
    if (cta < 64) {
        const int idx = cta * NTHR + tid;
        const int j = idx >> 5, b = idx & 31;
        const __nv_bfloat162 p =
            split2(h0[(size_t)layer * Bq * Hq + (size_t)b * Hq + j]);
        g_hb_hi[0][idx] = p.x;
        g_hb_lo[0][idx] = p.y;
    }

    const int bb = tid & 31;
    const int jl = tid >> 5;
    float c_reg = 0.f;
    if (tid < 128) c_reg = c0[(size_t)layer * Bq * Hq + (size_t)bb * Hq + jbase + jl];

    // reduce-index constants for this thread (o = tid, tid+256)
    int   g_off[2];
#pragma unroll
    for (int rep = 0; rep < 2; ++rep) {
        const int o = tid + rep * NTHR;
        const int r_idx = o >> 5, bo = o & 31;
        const int gate = r_idx >> 2, jj = r_idx & 3;
        g_off[rep] = (gate * Hq + jbase + jj) * Bq + bo;
    }

    unsigned gen = 0;
    for (int t = 0; t < Tq; ++t) {
        // ---- prefetch g_G[t] (independent of h; hides DRAM under barrier) ----
        float gp0 = g_G[(size_t)t * G4 * Bq + g_off[0]];
        float gp1 = g_G[(size_t)t * G4 * Bq + g_off[1]];

        // ---- global barrier ----
        gen += REC_NCTA;
        __threadfence();
        __syncthreads();
        if (tid == 0) {
            atomicAdd(&g_bar, 1u);
            while (*(volatile unsigned*)&g_bar < gen) { }
            __threadfence();
        }
        __syncthreads();

        const int cur = t & 1;

        // ---- stage h (hi/lo) into smem [k][40] ----
        {
            const uint4* shi = (const uint4*)g_hb_hi[cur];
            const uint4* slo = (const uint4*)g_hb_lo[cur];
#pragma unroll
            for (int it = 0; it < 8; ++it) {
                const int idx = tid + it * NTHR;     // 0..2047 (uint4 = 8 bf16)
                const int row = idx >> 2, c = idx & 3;
                *(uint4*)(Hhi + row * HP2 + c * 8) = shi[idx];
                *(uint4*)(Hlo + row * HP2 + c * 8) = slo[idx];
            }
        }
        __syncthreads();

        // ---- HMMA: 1 m-tile x 2 n-tiles x 4 k-steps, 3-term split ----
        {
            wmma::fragment<wmma::accumulator, 16, 16, 16, float> acc[2];
            wmma::fill_fragment(acc[0], 0.f);
            wmma::fill_fragment(acc[1], 0.f);
#pragma unroll
            for (int ks = 0; ks < 4; ++ks) {
                const int k = k0 + ks * 16;
#pragma unroll
                for (int jn = 0; jn < 2; ++jn) {
                    wmma::fragment<wmma::matrix_b, 16, 16, 16, __nv_bfloat16, wmma::row_major> b_hi, b_lo;
                    wmma::load_matrix_sync(b_hi, Hhi + k * HP2 + jn * 16, HP2);
                    wmma::load_matrix_sync(b_lo, Hlo + k * HP2 + jn * 16, HP2);
                    wmma::mma_sync(acc[jn], a_hi[ks], b_hi, acc[jn]);
                    wmma::mma_sync(acc[jn], a_hi[ks], b_lo, acc[jn]);
                    wmma::mma_sync(acc[jn], a_lo[ks], b_hi, acc[jn]);
                }
            }
            wmma::store_matrix_sync(red + w * 512 + 0,  acc[0], 32, wmma::mem_row_major);
            wmma::store_matrix_sync(red + w * 512 + 16, acc[1], 32, wmma::mem_row_major);
        }
        __syncthreads();

        // ---- reduce 8 k-slices + add prefetched input gates ----
#pragma unroll
        for (int rep = 0; rep < 2; ++rep) {
            const int o = tid + rep * NTHR;      // 0..511
            float s = (rep == 0 ? gp0 : gp1);
#pragma unroll
            for (int ww = 0; ww < 8; ++ww) s += red[ww * 512 + o];
            gsh[o] = s;
        }
        __syncthreads();

        // ---- activations + state update (torch gate order i,f,g,o) ----
        if (tid < 128) {
            const float xi = gsh[(0 * 4 + jl) * 32 + bb];
            const float xf = gsh[(1 * 4 + jl) * 32 + bb];
            const float xg = gsh[(2 * 4 + jl) * 32 + bb];
            const float xo = gsh[(3 * 4 + jl) * 32 + bb];
            const float ig = 1.f / (1.f + expf(-xi));
            const float fg = 1.f / (1.f + expf(-xf));
            const float gg = tanhf(xg);
            const float og = 1.f / (1.f + expf(-xo));
            c_reg = fg * c_reg + ig * gg;
            const float hv = og * tanhf(c_reg);
            const int j = jbase + jl;

            const __nv_bfloat162 hp = split2(hv);
            g_hb_hi[cur ^ 1][j * 32 + bb] = hp.x;
            g_hb_lo[cur ^ 1][j * 32 + bb] = hp.y;

            if (layer == 0) {
                g_hsplit[(size_t)(t * Bq + bb) * Hq + j] = hp;
            } else {
                out[((size_t)bb * Tq + t) * Hq + j] = hv;
            }
            if (t == Tq - 1) {
                out[(size_t)Bq * Tq * Hq + (size_t)layer * Bq * Hq + (size_t)bb * Hq + j] = hv;
                out[(size_t)Bq * Tq * Hq + (size_t)Lq * Bq * Hq
                    + (size_t)layer * Bq * Hq + (size_t)bb * Hq + j] = c_reg;
            }
        }
        // next iteration's barrier (fence + syncthreads) orders everything
    }
}

// ===========================================================================
// Launch: conv -> proj0 -> rec0 -> proj1 -> rec1
// ===========================================================================
extern "C" void kernel_launch(void* const* d_in, const int* in_sizes, int n_in,
                              void* d_out, int out_size)
{
    const float* x    = (const float*)d_in[0];
    const float* h0   = (const float*)d_in[1];
    const float* c0   = (const float*)d_in[2];
    const float* Wih  = (const float*)d_in[3];
    const float* Whh  = (const float*)d_in[4];
    const float* bih  = (const float*)d_in[5];
    const float* bhh  = (const float*)d_in[6];
    float* out = (float*)d_out;

    cudaFuncSetAttribute(lstm_rec, cudaFuncAttributeMaxDynamicSharedMemorySize, REC_SMEM);
    cudaFuncSetAttribute(proj_wmma, cudaFuncAttributeMaxDynamicSharedMemorySize, P_SMEM);

    void* barp = nullptr;
    cudaGetSymbolAddress(&barp, g_bar);

    __nv_bfloat162* xs = nullptr; cudaGetSymbolAddress((void**)&xs, g_xsplit);
    __nv_bfloat162* ws = nullptr; cudaGetSymbolAddress((void**)&ws, g_wsplit);

    const dim3 pgrid(G4 / 128, (Tq * Bq) / 64);

    // bf16 split conversions
    {
        const int n4x = Bq * Tq * Dq / 4;
        conv_split<<<(n4x + 255) / 256, 256>>>(x, xs, n4x);
        const int n4w = Lq * G4 * Dq / 4;
        conv_split<<<(n4w + 255) / 256, 256>>>(Wih, ws, n4w);
    }

    // Layer 0
    proj_wmma<<<pgrid, NTHR, P_SMEM>>>(bih, bhh, 0, 0);
    cudaMemsetAsync(barp, 0, sizeof(unsigned), 0);
    lstm_rec<<<REC_NCTA, NTHR, REC_SMEM>>>(h0, c0, Whh, out, 0);

    // Layer 1
    proj_wmma<<<pgrid, NTHR, P_SMEM>>>(bih, bhh, 1, 1);
    cudaMemsetAsync(barp, 0, sizeof(unsigned), 0);
    lstm_rec<<<REC_NCTA, NTHR, REC_SMEM>>>(h0, c0, Whh, out, 1);
}